// round 1
// baseline (speedup 1.0000x reference)
#include <cuda_runtime.h>
#include <math.h>

#define C 32
#define K 8
#define WARPS 8
#define RPW 4
#define ROWS_PER_BLK (WARPS * RPW)   // 32
#define NMAX 1500000

// Scratch (no allocations allowed)
__device__ float g_h1[(size_t)NMAX * C];      // conv1 raw output (192 MB)
__device__ float g_stats[4 * C];              // sum1, sq1, sum2, sq2
__device__ float g_scsh1[2 * C];              // bn1 scale/shift
__device__ float g_scsh2[2 * C];              // bn2 scale/shift

__global__ void zero_stats_kernel() {
    int t = threadIdx.x;
    if (t < 4 * C) g_stats[t] = 0.f;
}

// PASS 1: gather raw x.  PASS 2: gather relu(bn1(h1)) on the fly.
template <int PASS>
__global__ void __launch_bounds__(256, 3) conv_kernel(
    const float* __restrict__ xin,
    const int* __restrict__ nidx,
    const float* __restrict__ W,
    float* __restrict__ out,
    int n)
{
    extern __shared__ float smem[];
    float* Ws = smem;                        // K*C*C = 8192 floats
    float* Xs = smem + K * C * C;            // WARPS*K*RPW*C = 8192 floats
    float* bsum = Xs + WARPS * K * RPW * C;  // C
    float* bsq  = bsum + C;                  // C

    const int tid  = threadIdx.x;
    const int lane = tid & 31;
    const int warp = tid >> 5;

    // stage weights [k][ci][co] (same layout as input)
    #pragma unroll 4
    for (int i = tid; i < K * C * C; i += 256) Ws[i] = W[i];
    if (tid < C) { bsum[tid] = 0.f; bsq[tid] = 0.f; }

    float sc = 0.f, sh = 0.f;
    if (PASS == 2) { sc = g_scsh1[lane]; sh = g_scsh1[C + lane]; }
    __syncthreads();

    float tsum = 0.f, tsq = 0.f;
    float* myXs = Xs + warp * (K * RPW * C);

    const int groups = (n + ROWS_PER_BLK - 1) / ROWS_PER_BLK;
    for (int g = blockIdx.x; g < groups; g += gridDim.x) {
        const int row0 = g * ROWS_PER_BLK + warp * RPW;

        // one idx per lane: k = lane>>2, r = lane&3
        int rr = row0 + (lane & 3);
        int myidx = n;
        if (rr < n) myidx = nidx[(size_t)(lane >> 2) * n + rr];

        __syncwarp();
        // stage gathered rows: Xs[k][r][ci]  (conflict-free stores)
        #pragma unroll
        for (int k = 0; k < K; k++) {
            #pragma unroll
            for (int r = 0; r < RPW; r++) {
                int b = __shfl_sync(0xffffffffu, myidx, k * RPW + r);
                float v = 0.f;
                if (b < n) {
                    float t = xin[(size_t)b * C + lane];
                    if (PASS == 2) t = fmaxf(fmaf(t, sc, sh), 0.f);
                    v = t;
                }
                myXs[(k * RPW + r) * C + lane] = v;
            }
        }
        __syncwarp();

        // compute: lane = output channel, 4-row register blocking
        float acc0 = 0.f, acc1 = 0.f, acc2 = 0.f, acc3 = 0.f;
        #pragma unroll
        for (int k = 0; k < K; k++) {
            #pragma unroll
            for (int cc = 0; cc < C / 4; cc++) {
                const float w0 = Ws[(k * C + cc * 4 + 0) * C + lane];
                const float w1 = Ws[(k * C + cc * 4 + 1) * C + lane];
                const float w2 = Ws[(k * C + cc * 4 + 2) * C + lane];
                const float w3 = Ws[(k * C + cc * 4 + 3) * C + lane];
                const float4 x0 = *(const float4*)&myXs[(k * RPW + 0) * C + cc * 4];
                const float4 x1 = *(const float4*)&myXs[(k * RPW + 1) * C + cc * 4];
                const float4 x2 = *(const float4*)&myXs[(k * RPW + 2) * C + cc * 4];
                const float4 x3 = *(const float4*)&myXs[(k * RPW + 3) * C + cc * 4];
                acc0 = fmaf(x0.x, w0, acc0); acc1 = fmaf(x1.x, w0, acc1);
                acc2 = fmaf(x2.x, w0, acc2); acc3 = fmaf(x3.x, w0, acc3);
                acc0 = fmaf(x0.y, w1, acc0); acc1 = fmaf(x1.y, w1, acc1);
                acc2 = fmaf(x2.y, w1, acc2); acc3 = fmaf(x3.y, w1, acc3);
                acc0 = fmaf(x0.z, w2, acc0); acc1 = fmaf(x1.z, w2, acc1);
                acc2 = fmaf(x2.z, w2, acc2); acc3 = fmaf(x3.z, w2, acc3);
                acc0 = fmaf(x0.w, w3, acc0); acc1 = fmaf(x1.w, w3, acc1);
                acc2 = fmaf(x2.w, w3, acc2); acc3 = fmaf(x3.w, w3, acc3);
            }
        }

        // write + local BN stats
        const size_t orow = (size_t)row0 * C + lane;
        if (row0 + 0 < n) { out[orow + 0 * C] = acc0; tsum += acc0; tsq += acc0 * acc0; }
        if (row0 + 1 < n) { out[orow + 1 * C] = acc1; tsum += acc1; tsq += acc1 * acc1; }
        if (row0 + 2 < n) { out[orow + 2 * C] = acc2; tsum += acc2; tsq += acc2 * acc2; }
        if (row0 + 3 < n) { out[orow + 3 * C] = acc3; tsum += acc3; tsq += acc3 * acc3; }
    }

    // block-level stats reduction, then one global atomic per channel
    atomicAdd(&bsum[lane], tsum);
    atomicAdd(&bsq[lane], tsq);
    __syncthreads();
    if (tid < C) {
        const int off = (PASS == 1) ? 0 : 2 * C;
        atomicAdd(&g_stats[off + tid], bsum[tid]);
        atomicAdd(&g_stats[off + C + tid], bsq[tid]);
    }
}

__global__ void finalize_kernel(const float* __restrict__ gamma,
                                const float* __restrict__ beta,
                                int pass, float inv_n) {
    int c = threadIdx.x;
    if (c >= C) return;
    const int off = (pass == 1) ? 0 : 2 * C;
    float m = g_stats[off + c] * inv_n;
    float v = fmaxf(g_stats[off + C + c] * inv_n - m * m, 0.f);
    float s = gamma[c] * rsqrtf(v + 1e-5f);
    float* dst = (pass == 1) ? g_scsh1 : g_scsh2;
    dst[c] = s;
    dst[C + c] = beta[c] - m * s;
}

// out = bn2(h2) + x, vectorized
__global__ void epilogue_kernel(float* __restrict__ h,
                                const float* __restrict__ x,
                                long n4) {
    __shared__ float sc[C], sh[C];
    if (threadIdx.x < C) {
        sc[threadIdx.x] = g_scsh2[threadIdx.x];
        sh[threadIdx.x] = g_scsh2[C + threadIdx.x];
    }
    __syncthreads();
    long i = (long)blockIdx.x * blockDim.x + threadIdx.x;
    const long stride = (long)gridDim.x * blockDim.x;
    for (; i < n4; i += stride) {
        const int cb = (int)((i & 7) * 4);
        float4 hv = ((const float4*)h)[i];
        float4 xv = ((const float4*)x)[i];
        hv.x = fmaf(hv.x, sc[cb + 0], sh[cb + 0]) + xv.x;
        hv.y = fmaf(hv.y, sc[cb + 1], sh[cb + 1]) + xv.y;
        hv.z = fmaf(hv.z, sc[cb + 2], sh[cb + 2]) + xv.z;
        hv.w = fmaf(hv.w, sc[cb + 3], sh[cb + 3]) + xv.w;
        ((float4*)h)[i] = hv;
    }
}

extern "C" void kernel_launch(void* const* d_in, const int* in_sizes, int n_in,
                              void* d_out, int out_size) {
    const float* x   = (const float*)d_in[0];
    const int*   idx = (const int*)d_in[1];
    const float* W1  = (const float*)d_in[2];
    const float* g1  = (const float*)d_in[3];
    const float* b1  = (const float*)d_in[4];
    const float* W2  = (const float*)d_in[5];
    const float* g2  = (const float*)d_in[6];
    const float* b2  = (const float*)d_in[7];
    float* out = (float*)d_out;

    const int n = in_sizes[0] / C;

    float* h1 = nullptr;
    cudaGetSymbolAddress((void**)&h1, g_h1);

    const size_t smem = (size_t)(K * C * C + WARPS * K * RPW * C + 2 * C) * sizeof(float);
    cudaFuncSetAttribute(conv_kernel<1>, cudaFuncAttributeMaxDynamicSharedMemorySize, (int)smem);
    cudaFuncSetAttribute(conv_kernel<2>, cudaFuncAttributeMaxDynamicSharedMemorySize, (int)smem);

    const int blocks = 444;   // 3 blocks/SM * 148 SMs
    const float inv_n = 1.0f / (float)n;

    zero_stats_kernel<<<1, 128>>>();
    conv_kernel<1><<<blocks, 256, smem>>>(x, idx, W1, h1, n);
    finalize_kernel<<<1, 32>>>(g1, b1, 1, inv_n);
    conv_kernel<2><<<blocks, 256, smem>>>(h1, idx, W2, out, n);
    finalize_kernel<<<1, 32>>>(g2, b2, 2, inv_n);

    const long n4 = (long)n * C / 4;
    int eblocks = (int)((n4 + 255) / 256);
    if (eblocks > 69120) eblocks = 69120;
    epilogue_kernel<<<eblocks, 256>>>(out, x, n4);
}

// round 3
// speedup vs baseline: 2.6532x; 2.6532x over previous
#include <cuda_runtime.h>
#include <cuda_bf16.h>
#include <cstdint>

#define C 32
#define K 8
#define NMAX 1500000
#define THREADS 256
#define NWARP 8
#define TILE 256            // rows per CTA tile
#define WROWS 32            // rows per warp
#define ASTRIDE 80          // bytes per smem row: 32 bf16 (64B) + 16B pad -> conflict-free ldmatrix
#define BTILE (32 * ASTRIDE)          // one 32-row tile = 2560 B
#define OFF_B 0
#define B_BYTES (K * 2 * BTILE)       // 40960
#define OFF_A B_BYTES
#define AW_BYTES (2 * BTILE)          // per-warp staging (hi+lo)
#define SMEM_BYTES (OFF_A + NWARP * AW_BYTES)   // 81920
#define GRID_CONV 152

__device__ float g_h1[(size_t)NMAX * C];   // conv1 raw output scratch
__device__ float g_stats[4 * C];           // sum1, sq1, sum2, sq2
__device__ float g_scsh1[2 * C];
__device__ float g_scsh2[2 * C];

// ---------------- helpers ----------------
__device__ __forceinline__ uint32_t smem_u32(const void* p) {
    uint32_t a;
    asm("{ .reg .u64 t; cvta.to.shared.u64 t, %1; cvt.u32.u64 %0, t; }"
        : "=r"(a) : "l"(p));
    return a;
}

__device__ __forceinline__ void ldsm_x4(uint32_t* r, uint32_t addr) {
    asm volatile("ldmatrix.sync.aligned.m8n8.x4.shared.b16 {%0,%1,%2,%3}, [%4];"
                 : "=r"(r[0]), "=r"(r[1]), "=r"(r[2]), "=r"(r[3]) : "r"(addr));
}

__device__ __forceinline__ void mma_bf16(float* d, const uint32_t* a, const uint32_t* b) {
    asm volatile(
        "mma.sync.aligned.m16n8k16.row.col.f32.bf16.bf16.f32 "
        "{%0,%1,%2,%3}, {%4,%5,%6,%7}, {%8,%9}, {%0,%1,%2,%3};"
        : "+f"(d[0]), "+f"(d[1]), "+f"(d[2]), "+f"(d[3])
        : "r"(a[0]), "r"(a[1]), "r"(a[2]), "r"(a[3]), "r"(b[0]), "r"(b[1]));
}

__device__ __forceinline__ uint32_t pack2(float a, float b) {
    __nv_bfloat162 h = __floats2bfloat162_rn(a, b);   // .x=a (low), .y=b (high)
    return *reinterpret_cast<uint32_t*>(&h);
}

// ---------------- kernels ----------------
__global__ void zero_stats_kernel() {
    int t = threadIdx.x;
    if (t < 4 * C) g_stats[t] = 0.f;
}

// PASS 1: gather raw x. PASS 2: gather relu(bn1(h1)).
template <int PASS>
__global__ void __launch_bounds__(THREADS, 1) conv_kernel(
    const float* __restrict__ xin,
    const int* __restrict__ nidx,
    const float* __restrict__ Wsrc,
    float* __restrict__ out,
    int n)
{
    extern __shared__ char sm[];
    const uint32_t smb = smem_u32(sm);
    const int tid = threadIdx.x, lane = tid & 31, warp = tid >> 5;
    const int ch = lane & 7;                 // 4-channel chunk this lane gathers

    // Stage B^T: per (offset, var) a [co=32 rows][ci=32 bf16 cols] tile, stride 80B
    for (int i = tid; i < K * C * C; i += THREADS) {
        int off = i >> 10, ci = (i >> 5) & 31, co = i & 31;
        float w = Wsrc[i];
        __nv_bfloat16 wh = __float2bfloat16_rn(w);
        __nv_bfloat16 wl = __float2bfloat16_rn(w - __bfloat162float(wh));
        char* bb = sm + OFF_B + (size_t)(off * 2) * BTILE + co * ASTRIDE + ci * 2;
        *(__nv_bfloat16*)bb = wh;
        *(__nv_bfloat16*)(bb + BTILE) = wl;
    }

    float4 scv = make_float4(0, 0, 0, 0), shv = scv;   // bn1 params (PASS 2)
    if (PASS == 2) {
        scv = *(const float4*)(g_scsh1 + ch * 4);
        shv = *(const float4*)(g_scsh1 + C + ch * 4);
    }
    __syncthreads();

    char* aw = sm + OFF_A + (size_t)warp * AW_BYTES;
    const uint32_t a_base = smb + OFF_A + warp * AW_BYTES;

    float ssum[8], ssq[8];
    #pragma unroll
    for (int j = 0; j < 8; j++) { ssum[j] = 0.f; ssq[j] = 0.f; }

    const int tiles = (n + TILE - 1) / TILE;
    for (int t = blockIdx.x; t < tiles; t += gridDim.x) {
        const int row0w = t * TILE + warp * WROWS;
        const int R = row0w + lane;          // this lane owns idx for local row `lane`
        const bool rv = (R < n);

        float acc[2][4][4];
        #pragma unroll
        for (int mt = 0; mt < 2; mt++)
            #pragma unroll
            for (int nt = 0; nt < 4; nt++)
                #pragma unroll
                for (int j = 0; j < 4; j++) acc[mt][nt][j] = 0.f;

        // -------- software pipeline over the 8 kernel offsets --------
        float4 gcur[8];
        int idx_next;
        {
            int i0 = rv ? nidx[R] : n;
            #pragma unroll
            for (int p = 0; p < 8; p++) {
                int b = __shfl_sync(0xffffffffu, i0, (lane >> 3) + 4 * p);
                float4 f = make_float4(0, 0, 0, 0);
                if (b < n) f = *(const float4*)(xin + (size_t)b * C + ch * 4);
                gcur[p] = f;
            }
            idx_next = rv ? nidx[(size_t)n + R] : n;
        }

        #pragma unroll
        for (int off = 0; off < K; off++) {
            // STS current offset (hi/lo split + optional bn1+relu)
            #pragma unroll
            for (int p = 0; p < 8; p++) {
                float4 f = gcur[p];
                if (PASS == 2) {
                    f.x = fmaxf(fmaf(f.x, scv.x, shv.x), 0.f);
                    f.y = fmaxf(fmaf(f.y, scv.y, shv.y), 0.f);
                    f.z = fmaxf(fmaf(f.z, scv.z, shv.z), 0.f);
                    f.w = fmaxf(fmaf(f.w, scv.w, shv.w), 0.f);
                }
                __nv_bfloat16 hx = __float2bfloat16_rn(f.x);
                __nv_bfloat16 hy = __float2bfloat16_rn(f.y);
                __nv_bfloat16 hz = __float2bfloat16_rn(f.z);
                __nv_bfloat16 hw = __float2bfloat16_rn(f.w);
                float lx = f.x - __bfloat162float(hx);
                float ly = f.y - __bfloat162float(hy);
                float lz = f.z - __bfloat162float(hz);
                float lw = f.w - __bfloat162float(hw);
                uint32_t h0 = ((uint32_t)*(uint16_t*)&hy << 16) | *(uint16_t*)&hx;
                uint32_t h1 = ((uint32_t)*(uint16_t*)&hw << 16) | *(uint16_t*)&hz;
                const int r = (lane >> 3) + 4 * p;
                *(uint2*)(aw + r * ASTRIDE + ch * 8) = make_uint2(h0, h1);
                *(uint2*)(aw + BTILE + r * ASTRIDE + ch * 8) =
                    make_uint2(pack2(lx, ly), pack2(lz, lw));
            }

            // prefetch gathers for off+1 and idx for off+2 (hidden under mma)
            float4 gnext[8];
            if (off < K - 1) {
                #pragma unroll
                for (int p = 0; p < 8; p++) {
                    int b = __shfl_sync(0xffffffffu, idx_next, (lane >> 3) + 4 * p);
                    float4 f = make_float4(0, 0, 0, 0);
                    if (b < n) f = *(const float4*)(xin + (size_t)b * C + ch * 4);
                    gnext[p] = f;
                }
            }
            if (off < K - 2) idx_next = rv ? nidx[(size_t)(off + 2) * n + R] : n;

            __syncwarp();
            // -------- compute: 2 k-tiles x (ldmatrix + 24 mma) --------
            const uint32_t arow = (lane & 15);
            const uint32_t bn = ((lane & 16) >> 1) + (lane & 7);
            #pragma unroll
            for (int kt = 0; kt < 2; kt++) {
                const uint32_t acol = kt * 32 + ((lane >> 4) << 4);
                const uint32_t bcol = kt * 32 + ((lane & 8) << 1);
                uint32_t ah[2][4], al[2][4];         // [mt]
                uint32_t bh[2][4], bl[2][4];         // [npair] -> frags for 2 n-tiles
                #pragma unroll
                for (int mt = 0; mt < 2; mt++) {
                    ldsm_x4(ah[mt], a_base + (mt * 16 + arow) * ASTRIDE + acol);
                    ldsm_x4(al[mt], a_base + BTILE + (mt * 16 + arow) * ASTRIDE + acol);
                }
                const uint32_t b_base = smb + OFF_B + (off * 2) * BTILE;
                #pragma unroll
                for (int p = 0; p < 2; p++) {
                    ldsm_x4(bh[p], b_base + (p * 16 + bn) * ASTRIDE + bcol);
                    ldsm_x4(bl[p], b_base + BTILE + (p * 16 + bn) * ASTRIDE + bcol);
                }
                #pragma unroll
                for (int mt = 0; mt < 2; mt++)
                    #pragma unroll
                    for (int p = 0; p < 2; p++)
                        #pragma unroll
                        for (int h = 0; h < 2; h++) {
                            float* d = acc[mt][p * 2 + h];
                            mma_bf16(d, ah[mt], &bh[p][h * 2]);   // xh*wh
                            mma_bf16(d, ah[mt], &bl[p][h * 2]);   // xh*wl
                            mma_bf16(d, al[mt], &bh[p][h * 2]);   // xl*wh
                        }
            }
            __syncwarp();

            if (off < K - 1) {
                #pragma unroll
                for (int p = 0; p < 8; p++) gcur[p] = gnext[p];
            }
        }

        // -------- store + fused BN stats --------
        #pragma unroll
        for (int mt = 0; mt < 2; mt++) {
            const int r0 = row0w + mt * 16 + (lane >> 2);
            #pragma unroll
            for (int nt = 0; nt < 4; nt++) {
                const int cc = nt * 8 + (lane & 3) * 2;
                float* d = acc[mt][nt];
                if (r0 < n)
                    *(float2*)(out + (size_t)r0 * C + cc) = make_float2(d[0], d[1]);
                if (r0 + 8 < n)
                    *(float2*)(out + (size_t)(r0 + 8) * C + cc) = make_float2(d[2], d[3]);
                const int j = nt * 2;
                ssum[j]     += d[0] + d[2];
                ssq[j]      += d[0] * d[0] + d[2] * d[2];
                ssum[j + 1] += d[1] + d[3];
                ssq[j + 1]  += d[1] * d[1] + d[3] * d[3];
            }
        }
    }

    // -------- per-CTA stats reduction, one global atomic per channel --------
    __syncthreads();
    float* red = (float*)sm;
    if (tid < 2 * C) red[tid] = 0.f;
    __syncthreads();
    #pragma unroll
    for (int j = 0; j < 8; j++) {
        const int c = (j >> 1) * 8 + (lane & 3) * 2 + (j & 1);
        atomicAdd(&red[c], ssum[j]);
        atomicAdd(&red[C + c], ssq[j]);
    }
    __syncthreads();
    if (tid < 2 * C)
        atomicAdd(&g_stats[(PASS == 1 ? 0 : 2 * C) + tid], red[tid]);
}

__global__ void finalize_kernel(const float* __restrict__ gamma,
                                const float* __restrict__ beta,
                                int pass, float inv_n) {
    int c = threadIdx.x;
    if (c >= C) return;
    const int off = (pass == 1) ? 0 : 2 * C;
    float m = g_stats[off + c] * inv_n;
    float v = fmaxf(g_stats[off + C + c] * inv_n - m * m, 0.f);
    float s = gamma[c] * rsqrtf(v + 1e-5f);
    float* dst = (pass == 1) ? g_scsh1 : g_scsh2;
    dst[c] = s;
    dst[C + c] = beta[c] - m * s;
}

// out = bn2(h2) + x
__global__ void epilogue_kernel(float* __restrict__ h,
                                const float* __restrict__ x,
                                long n4) {
    __shared__ float sc[C], sh[C];
    if (threadIdx.x < C) {
        sc[threadIdx.x] = g_scsh2[threadIdx.x];
        sh[threadIdx.x] = g_scsh2[C + threadIdx.x];
    }
    __syncthreads();
    long i = (long)blockIdx.x * blockDim.x + threadIdx.x;
    const long stride = (long)gridDim.x * blockDim.x;
    for (; i < n4; i += stride) {
        const int cb = (int)((i & 7) * 4);
        float4 hv = ((const float4*)h)[i];
        float4 xv = ((const float4*)x)[i];
        hv.x = fmaf(hv.x, sc[cb + 0], sh[cb + 0]) + xv.x;
        hv.y = fmaf(hv.y, sc[cb + 1], sh[cb + 1]) + xv.y;
        hv.z = fmaf(hv.z, sc[cb + 2], sh[cb + 2]) + xv.z;
        hv.w = fmaf(hv.w, sc[cb + 3], sh[cb + 3]) + xv.w;
        ((float4*)h)[i] = hv;
    }
}

extern "C" void kernel_launch(void* const* d_in, const int* in_sizes, int n_in,
                              void* d_out, int out_size) {
    const float* x   = (const float*)d_in[0];
    const int*   idx = (const int*)d_in[1];
    const float* W1  = (const float*)d_in[2];
    const float* g1  = (const float*)d_in[3];
    const float* b1  = (const float*)d_in[4];
    const float* W2  = (const float*)d_in[5];
    const float* g2  = (const float*)d_in[6];
    const float* b2  = (const float*)d_in[7];
    float* out = (float*)d_out;

    const int n = in_sizes[0] / C;
    const float inv_n = 1.0f / (float)n;

    float* h1 = nullptr;
    cudaGetSymbolAddress((void**)&h1, g_h1);

    cudaFuncSetAttribute(conv_kernel<1>, cudaFuncAttributeMaxDynamicSharedMemorySize, SMEM_BYTES);
    cudaFuncSetAttribute(conv_kernel<2>, cudaFuncAttributeMaxDynamicSharedMemorySize, SMEM_BYTES);

    zero_stats_kernel<<<1, 128>>>();
    conv_kernel<1><<<GRID_CONV, THREADS, SMEM_BYTES>>>(x, idx, W1, h1, n);
    finalize_kernel<<<1, 32>>>(g1, b1, 1, inv_n);
    conv_kernel<2><<<GRID_CONV, THREADS, SMEM_BYTES>>>(h1, idx, W2, out, n);
    finalize_kernel<<<1, 32>>>(g2, b2, 2, inv_n);

    const long n4 = (long)n * C / 4;
    int eblocks = (int)((n4 + 255) / 256);
    if (eblocks > 69120) eblocks = 69120;
    epilogue_kernel<<<eblocks, 256>>>(out, x, n4);
}